// round 5
// baseline (speedup 1.0000x reference)
#include <cuda_runtime.h>
#include <stdint.h>

// Problem shape is fixed: 32 images, 512x512, 1 channel, float32.
#define NIMG 32
#define H    512
#define WPX  512
#define WPR  16                       // 32-bit words per row (512/32)
#define NWORDS (NIMG * H * WPR)       // 262144 words = 1 MB
#define SEGROWS 128                   // rows per CTA (H / CLUSTER)
#define CLUSTER 4
#define TPB 512
#define SIDX 132                      // smem rows: idx = local_row + 2, 0..131

// Packed bit buffer (device global: no allocation allowed).
__device__ uint32_t g_bufA[NWORDS];

// ---------------------------------------------------------------------------
// Pack: one warp -> 512 pixels -> 16 words. 16 independent coalesced loads per
// thread (MLP=16), 16 ballots (warp-uniform), lane 0 stores 4x STG.128.
// ---------------------------------------------------------------------------
__global__ void __launch_bounds__(256) pack_kernel(const float* __restrict__ in) {
    int warpId = (blockIdx.x * blockDim.x + threadIdx.x) >> 5;
    int lane   = threadIdx.x & 31;
    int pbase  = warpId * 512;                 // pixel base for this warp

    float v[16];
    #pragma unroll
    for (int j = 0; j < 16; ++j) v[j] = in[pbase + j * 32 + lane];

    uint32_t b[16];
    #pragma unroll
    for (int j = 0; j < 16; ++j) b[j] = __ballot_sync(0xffffffffu, v[j] >= 0.5f);

    if (lane == 0) {
        int wbase = pbase >> 5;
        #pragma unroll
        for (int j = 0; j < 4; ++j)
            *(uint4*)&g_bufA[wbase + j * 4] =
                make_uint4(b[j*4], b[j*4+1], b[j*4+2], b[j*4+3]);
    }
}

// ---------------------------------------------------------------------------
// Unpack: one thread -> 8 pixels via two STG.128.
// ---------------------------------------------------------------------------
__global__ void __launch_bounds__(256) unpack_kernel(float* __restrict__ out) {
    int tid = blockIdx.x * blockDim.x + threadIdx.x;   // 0 .. NPIX/8-1
    uint32_t w = g_bufA[tid >> 2];
    int sh = (tid & 3) * 8;
    float4 a, b;
    a.x = (float)((w >> (sh + 0)) & 1u);
    a.y = (float)((w >> (sh + 1)) & 1u);
    a.z = (float)((w >> (sh + 2)) & 1u);
    a.w = (float)((w >> (sh + 3)) & 1u);
    b.x = (float)((w >> (sh + 4)) & 1u);
    b.y = (float)((w >> (sh + 5)) & 1u);
    b.z = (float)((w >> (sh + 6)) & 1u);
    b.w = (float)((w >> (sh + 7)) & 1u);
    *(float4*)&out[tid * 8]     = a;
    *(float4*)&out[tid * 8 + 4] = b;
}

__device__ __forceinline__ uint32_t maj3(uint32_t a, uint32_t b, uint32_t c) {
    return (a & b) | (c & (a | b));    // 1 LOP3
}

// DSMEM store of a word into cluster CTA `rank`'s shared memory.
__device__ __forceinline__ void dsmem_st(uint32_t* p, uint32_t rank, uint32_t v) {
    uint32_t a = (uint32_t)__cvta_generic_to_shared(p);
    uint32_t ra;
    asm volatile("mapa.shared::cluster.u32 %0, %1, %2;" : "=r"(ra) : "r"(a), "r"(rank));
    asm volatile("st.shared::cluster.u32 [%0], %1;" :: "r"(ra), "r"(v) : "memory");
}

__device__ __forceinline__ void cluster_barrier() {
    asm volatile("barrier.cluster.arrive.aligned;" ::: "memory");
    asm volatile("barrier.cluster.wait.aligned;" ::: "memory");
}

// Zhang-Suen delete mask for one 32-pixel word, given the 8 neighbor masks.
// acnt==1 computed as acnt<=1 (valid since 2<=bcnt<=6 implies acnt>=1).
template<bool FIRST>
__device__ __forceinline__ uint32_t word_update(
    uint32_t mi, uint32_t P2, uint32_t P3, uint32_t P4, uint32_t P5,
    uint32_t P6, uint32_t P7, uint32_t P8, uint32_t P9)
{
    // ---- bcnt via CSA: need 2 <= bcnt <= 6 ----
    uint32_t sa = P2 ^ P3 ^ P4, ca = maj3(P2, P3, P4);
    uint32_t sb = P5 ^ P6 ^ P7, cb = maj3(P5, P6, P7);
    uint32_t sc = P8 ^ P9,      cc = P8 & P9;
    uint32_t S0s = sa ^ sb ^ sc, C1 = maj3(sa, sb, sc);
    uint32_t S1s = ca ^ cb ^ cc, C2 = maj3(ca, cb, cc);
    uint32_t ge2 = C1 | S1s | C2;
    uint32_t ge7 = C2 & ((C1 & S1s) | ((C1 ^ S1s) & S0s));

    // ---- acnt <= 1: all carries of the transition CSA are zero ----
    uint32_t t0 = ~P2 & P3, t1 = ~P3 & P4, t2 = ~P4 & P5, t3 = ~P5 & P6;
    uint32_t t4 = ~P6 & P7, t5 = ~P7 & P8, t6 = ~P8 & P9, t7 = ~P9 & P2;
    uint32_t aca = maj3(t0, t1, t2);
    uint32_t acb = maj3(t3, t4, t5);
    uint32_t acc = t6 & t7;
    uint32_t asa = t0 ^ t1 ^ t2;
    uint32_t asb = t3 ^ t4 ^ t5;
    uint32_t asc = t6 ^ t7;
    uint32_t A1  = maj3(asa, asb, asc);
    uint32_t ex1 = ~(A1 | aca | acb) & ~acc;

    // ---- c1 & c2 ----
    uint32_t inner;
    if (FIRST) inner = (P4 & P6) & (P2 | P8);
    else       inner = (P2 & P8) & (P4 | P6);

    uint32_t del = ge2 & ~ge7 & ex1 & ~inner;
    return mi & ~del;
}

// Compute 4 output words (quarter row q of smem row index i): S -> D.
template<bool FIRST>
__device__ __forceinline__ void strip4(
    const uint32_t* __restrict__ S, uint32_t* __restrict__ D, int i, int q)
{
    int base = i * WPR + q * 4;

    uint4 m4 = *(const uint4*)&S[base];
    uint4 u4 = *(const uint4*)&S[base - WPR];
    uint4 d4 = *(const uint4*)&S[base + WPR];
    uint32_t ml = q ? S[base - 1]       : 0u, mr = (q < 3) ? S[base + 4]       : 0u;
    uint32_t ul = q ? S[base - WPR - 1] : 0u, ur = (q < 3) ? S[base - WPR + 4] : 0u;
    uint32_t dl = q ? S[base + WPR - 1] : 0u, dr = (q < 3) ? S[base + WPR + 4] : 0u;

    uint32_t u[4] = {u4.x, u4.y, u4.z, u4.w};
    uint32_t m[4] = {m4.x, m4.y, m4.z, m4.w};
    uint32_t d[4] = {d4.x, d4.y, d4.z, d4.w};
    uint32_t o[4];

    #pragma unroll
    for (int j = 0; j < 4; ++j) {
        uint32_t up = u[j], mi = m[j], dn = d[j];
        uint32_t upl = j ? u[j - 1] : ul, upr = (j < 3) ? u[j + 1] : ur;
        uint32_t mil = j ? m[j - 1] : ml, mir = (j < 3) ? m[j + 1] : mr;
        uint32_t dnl = j ? d[j - 1] : dl, dnr = (j < 3) ? d[j + 1] : dr;

        uint32_t P2 = up;
        uint32_t P3 = __funnelshift_r(up, upr, 1);
        uint32_t P4 = __funnelshift_r(mi, mir, 1);
        uint32_t P5 = __funnelshift_r(dn, dnr, 1);
        uint32_t P6 = dn;
        uint32_t P7 = __funnelshift_l(dnl, dn, 1);
        uint32_t P8 = __funnelshift_l(mil, mi, 1);
        uint32_t P9 = __funnelshift_l(upl, up, 1);

        o[j] = word_update<FIRST>(mi, P2, P3, P4, P5, P6, P7, P8, P9);
    }

    *(uint4*)&D[base] = make_uint4(o[0], o[1], o[2], o[3]);
}

// ---------------------------------------------------------------------------
// Persistent cluster kernel with depth-2 ghost zones, push-model halos.
// Grid = 128 CTAs (32 images x 4 segments), cluster = 4 (one image).
//
// Smem layout: S0 rows idx 0..131 (local row r at idx r+2); idx 0,1/130,131
// are the WORKING ghost rows read by substep A. PG[2][4][16] are parity-
// double-buffered push targets (slots 0,1 = rows -2,-1; slots 2,3 = 128,129).
// Per 2 substeps: copy PG[p] -> working ghosts, A over 130 rows (idx 1..130)
// S0->S1, B over 128 rows (idx 2..129) S1->S0, push boundary rows to
// neighbors' PG[p^1], ONE cluster barrier. A neighbor can run at most one
// barrier window ahead; it then writes parity p^1 while we read p: race-free.
// Deletion-only updates keep out-of-image ghost rows identically zero.
// ---------------------------------------------------------------------------
__global__ void __cluster_dims__(CLUSTER, 1, 1) __launch_bounds__(TPB, 1)
skeleton_cluster_kernel() {
    __shared__ uint32_t S0[SIDX * WPR];
    __shared__ uint32_t S1[SIDX * WPR];
    __shared__ uint32_t PG[2][4][WPR];

    int tid   = threadIdx.x;
    int rank  = blockIdx.x & (CLUSTER - 1);
    int gbase = blockIdx.x * (SEGROWS * WPR);     // img*8192 + seg*2048

    // Load own 2048 words into S0 idx 2..129 (one uint4 per thread).
    *(uint4*)&S0[2 * WPR + tid * 4] = *(const uint4*)&g_bufA[gbase + tid * 4];

    // Zero the never-pushed ghost parity slots at image boundaries.
    if (rank == 0 && tid < 64)
        PG[tid >> 5][(tid >> 4) & 1][tid & 15] = 0u;          // top slots 0,1
    if (rank == CLUSTER - 1 && tid < 64)
        PG[tid >> 5][2 + ((tid >> 4) & 1)][tid & 15] = 0u;    // bottom slots 2,3
    __syncthreads();

    // Initial push into parity 0.
    {
        int w = tid & 15, r = tid >> 4;
        if (tid < 32) {            // our rows 0,1 -> prev's bottom slots 2,3
            if (rank > 0) dsmem_st(&PG[0][2 + r][w], (uint32_t)(rank - 1),
                                   S0[(2 + r) * WPR + w]);
        } else if (tid < 64) {     // our rows 126,127 -> next's top slots 0,1
            int rr = r - 2;
            if (rank < CLUSTER - 1) dsmem_st(&PG[0][rr][w], (uint32_t)(rank + 1),
                                             S0[(128 + rr) * WPR + w]);
        }
    }
    cluster_barrier();

    #pragma unroll 1
    for (int it = 0; it < 8; ++it) {
        // Copy parity ghosts into working rows 0,1,130,131.
        if (tid < 64) {
            int r4 = tid >> 4, w = tid & 15;
            int di = (r4 < 2) ? r4 : (128 + r4);
            S0[di * WPR + w] = PG[it & 1][r4][w];
        }
        __syncthreads();

        // Substep A: 130 rows (idx 1..130) = 520 quarter-row strips.
        strip4<true>(S0, S1, 1 + (tid >> 2), tid & 3);
        if (tid < 8) strip4<true>(S0, S1, 1 + ((512 + tid) >> 2), (512 + tid) & 3);
        __syncthreads();

        // Substep B: 128 rows (idx 2..129) = 512 strips.
        strip4<false>(S1, S0, 2 + (tid >> 2), tid & 3);
        __syncthreads();

        if (it < 7) {
            int w = tid & 15, r = tid >> 4, p = (it + 1) & 1;
            if (tid < 32) {
                if (rank > 0) dsmem_st(&PG[p][2 + r][w], (uint32_t)(rank - 1),
                                       S0[(2 + r) * WPR + w]);
            } else if (tid < 64) {
                int rr = r - 2;
                if (rank < CLUSTER - 1) dsmem_st(&PG[p][rr][w], (uint32_t)(rank + 1),
                                                 S0[(128 + rr) * WPR + w]);
            }
            cluster_barrier();
        }
    }

    // Write back S0 idx 2..129 (no remote accesses after the last barrier).
    *(uint4*)&g_bufA[gbase + tid * 4] = *(const uint4*)&S0[2 * WPR + tid * 4];
}

extern "C" void kernel_launch(void* const* d_in, const int* in_sizes, int n_in,
                              void* d_out, int out_size) {
    (void)in_sizes; (void)n_in; (void)out_size;
    const float* in = (const float*)d_in[0];
    float* out = (float*)d_out;

    const int NPIX = NIMG * H * WPX;                  // 8388608
    pack_kernel<<<NPIX / (256 * 16), 256>>>(in);      // 16 px/thread

    skeleton_cluster_kernel<<<NIMG * CLUSTER, TPB>>>();

    unpack_kernel<<<NPIX / (256 * 8), 256>>>(out);    // 8 px/thread
}